// round 2
// baseline (speedup 1.0000x reference)
#include <cuda_runtime.h>
#include <cuda_bf16.h>
#include <cstdint>

// Problem constants (fixed by the dataset: B=32, H=W=56, C=384, heads=12, ws=7)
#define B_SZ    32
#define HW      56
#define L_TOK   3136            // 56*56
#define M_TOK   100352          // 32*3136
#define C_DIM   384
#define N_QKV   1152
#define HEADS   12
#define HD      32
#define WS      7
#define LW      49              // tokens per window
#define NWIN    2048            // 32 * 8 * 8

// Scratch (device globals; allocation-free per harness rules)
__device__ float g_qkv[(size_t)M_TOK * N_QKV];   // ~441 MiB
__device__ float g_attn[(size_t)M_TOK * C_DIM];  // ~147 MiB

// ---------------------------------------------------------------------------
// SGEMM: C[M,N] = A[M,K] * W[N,K]^T + bias[N]   (K = 384 fixed)
// 128x128 tile, BK=8, 8x8 per-thread microtile, 256 threads.
// ---------------------------------------------------------------------------
__global__ __launch_bounds__(256) void sgemm_tn(
    const float* __restrict__ A,      // [M, 384] row-major
    const float* __restrict__ W,      // [N, 384] row-major
    const float* __restrict__ bias,   // [N]
    float* __restrict__ C,            // [M, N]
    int N)
{
    const int K = C_DIM;
    __shared__ float As[8][128];
    __shared__ float Bs[8][128];

    const int tid = threadIdx.x;
    const int bm = blockIdx.y;
    const int bn = blockIdx.x;

    const float* Ablk = A + (size_t)bm * 128 * K;
    const float* Wblk = W + (size_t)bn * 128 * K;

    const int lr = tid >> 1;            // 0..127 (row within tile)
    const int lc = (tid & 1) * 4;       // 0 or 4 (k offset)

    const int tr = (tid >> 4) * 8;      // thread micro-tile row base
    const int tc = (tid & 15) * 8;      // thread micro-tile col base

    float acc[8][8];
    #pragma unroll
    for (int i = 0; i < 8; i++)
        #pragma unroll
        for (int j = 0; j < 8; j++) acc[i][j] = 0.0f;

    for (int k0 = 0; k0 < K; k0 += 8) {
        float4 a = *(const float4*)(Ablk + (size_t)lr * K + k0 + lc);
        float4 b = *(const float4*)(Wblk + (size_t)lr * K + k0 + lc);
        As[lc + 0][lr] = a.x; As[lc + 1][lr] = a.y;
        As[lc + 2][lr] = a.z; As[lc + 3][lr] = a.w;
        Bs[lc + 0][lr] = b.x; Bs[lc + 1][lr] = b.y;
        Bs[lc + 2][lr] = b.z; Bs[lc + 3][lr] = b.w;
        __syncthreads();

        #pragma unroll
        for (int k = 0; k < 8; k++) {
            float ra[8], rb[8];
            #pragma unroll
            for (int i = 0; i < 8; i++) ra[i] = As[k][tr + i];
            #pragma unroll
            for (int j = 0; j < 8; j++) rb[j] = Bs[k][tc + j];
            #pragma unroll
            for (int i = 0; i < 8; i++)
                #pragma unroll
                for (int j = 0; j < 8; j++)
                    acc[i][j] = fmaf(ra[i], rb[j], acc[i][j]);
        }
        __syncthreads();
    }

    // Epilogue with bias, vectorized stores
    #pragma unroll
    for (int i = 0; i < 8; i++) {
        const size_t m = (size_t)bm * 128 + tr + i;
        #pragma unroll
        for (int j = 0; j < 8; j += 4) {
            const int n = bn * 128 + tc + j;
            float4 v;
            v.x = acc[i][j + 0] + bias[n + 0];
            v.y = acc[i][j + 1] + bias[n + 1];
            v.z = acc[i][j + 2] + bias[n + 2];
            v.w = acc[i][j + 3] + bias[n + 3];
            *(float4*)(C + m * N + n) = v;
        }
    }
}

// ---------------------------------------------------------------------------
// Window attention: one block per (window, head). 64 threads, thread i < 49
// owns query row i. Q/K/V staged in smem as float4 rows of 8.
// ---------------------------------------------------------------------------
__global__ __launch_bounds__(64) void win_attn(void)
{
    const int head = blockIdx.x;       // 0..11
    const int win  = blockIdx.y;       // 0..2047
    const int b  = win >> 6;           // /64
    const int wi = win & 63;
    const int wh = wi >> 3;            // window row
    const int ww = wi & 7;             // window col

    __shared__ float4 Qs[LW * 8];
    __shared__ float4 Ks[LW * 8];
    __shared__ float4 Vs[LW * 8];

    const int tid = threadIdx.x;
    const int head_off = head * HD;    // floats

    // Stage Q, K, V for this window/head
    for (int idx = tid; idx < LW * 8; idx += 64) {
        const int j  = idx >> 3;       // token in window
        const int dd = idx & 7;        // float4 index within hd=32
        const int r = j / WS, c = j % WS;
        const int l = (wh * WS + r) * HW + (ww * WS + c);
        const size_t base = ((size_t)b * L_TOK + l) * N_QKV + head_off + dd * 4;
        Qs[idx] = *(const float4*)(g_qkv + base);
        Ks[idx] = *(const float4*)(g_qkv + base + C_DIM);
        Vs[idx] = *(const float4*)(g_qkv + base + 2 * C_DIM);
    }
    __syncthreads();

    if (tid >= LW) return;
    const int i = tid;

    const float scale = 0.17677669529663687f;  // 32^-0.5

    float4 q4[8];
    #pragma unroll
    for (int dd = 0; dd < 8; dd++) {
        float4 q = Qs[i * 8 + dd];
        q.x *= scale; q.y *= scale; q.z *= scale; q.w *= scale;
        q4[dd] = q;
    }

    float s[LW];
    float mx = -1e30f;
    #pragma unroll 7
    for (int j = 0; j < LW; j++) {
        float acc = 0.0f;
        #pragma unroll
        for (int dd = 0; dd < 8; dd++) {
            const float4 k4 = Ks[j * 8 + dd];
            acc = fmaf(q4[dd].x, k4.x, acc);
            acc = fmaf(q4[dd].y, k4.y, acc);
            acc = fmaf(q4[dd].z, k4.z, acc);
            acc = fmaf(q4[dd].w, k4.w, acc);
        }
        s[j] = acc;
        mx = fmaxf(mx, acc);
    }

    float sum = 0.0f;
    #pragma unroll 7
    for (int j = 0; j < LW; j++) {
        const float e = __expf(s[j] - mx);
        s[j] = e;
        sum += e;
    }
    const float inv = 1.0f / sum;

    float4 o4[8];
    #pragma unroll
    for (int dd = 0; dd < 8; dd++) o4[dd] = make_float4(0.f, 0.f, 0.f, 0.f);

    #pragma unroll 7
    for (int j = 0; j < LW; j++) {
        const float p = s[j];
        #pragma unroll
        for (int dd = 0; dd < 8; dd++) {
            const float4 v4 = Vs[j * 8 + dd];
            o4[dd].x = fmaf(p, v4.x, o4[dd].x);
            o4[dd].y = fmaf(p, v4.y, o4[dd].y);
            o4[dd].z = fmaf(p, v4.z, o4[dd].z);
            o4[dd].w = fmaf(p, v4.w, o4[dd].w);
        }
    }

    // Write back to original token order (window_reverse is identity here)
    const int r = i / WS, c = i % WS;
    const int l = (wh * WS + r) * HW + (ww * WS + c);
    float* dst = g_attn + ((size_t)b * L_TOK + l) * C_DIM + head_off;
    #pragma unroll
    for (int dd = 0; dd < 8; dd++) {
        float4 o = o4[dd];
        o.x *= inv; o.y *= inv; o.z *= inv; o.w *= inv;
        ((float4*)dst)[dd] = o;
    }
}

// ---------------------------------------------------------------------------
extern "C" void kernel_launch(void* const* d_in, const int* in_sizes, int n_in,
                              void* d_out, int out_size)
{
    const float* x      = (const float*)d_in[0];
    const float* qkv_w  = (const float*)d_in[1];
    const float* qkv_b  = (const float*)d_in[2];
    const float* proj_w = (const float*)d_in[3];
    const float* proj_b = (const float*)d_in[4];
    float* out = (float*)d_out;

    float* qkv_buf = nullptr;
    float* attn_buf = nullptr;
    cudaGetSymbolAddress((void**)&qkv_buf, g_qkv);
    cudaGetSymbolAddress((void**)&attn_buf, g_attn);

    // 1) QKV GEMM: [100352,384] x [1152,384]^T -> [100352,1152]
    {
        dim3 grid(N_QKV / 128, M_TOK / 128);   // (9, 784)
        sgemm_tn<<<grid, 256>>>(x, qkv_w, qkv_b, qkv_buf, N_QKV);
    }
    // 2) Windowed attention
    {
        dim3 grid(HEADS, NWIN);                // (12, 2048)
        win_attn<<<grid, 64>>>();
    }
    // 3) Proj GEMM: [100352,384] x [384,384]^T -> output
    {
        dim3 grid(C_DIM / 128, M_TOK / 128);   // (3, 784)
        sgemm_tn<<<grid, 256>>>(attn_buf, proj_w, proj_b, out, C_DIM);
    }
}

// round 6
// speedup vs baseline: 1.3353x; 1.3353x over previous
#include <cuda_runtime.h>
#include <cuda_bf16.h>
#include <cstdint>

// Problem constants (B=32, H=W=56, C=384, heads=12, ws=7)
#define HW      56
#define L_TOK   3136
#define M_TOK   100352
#define C_DIM   384
#define N_QKV   1152
#define HEADS   12
#define HD      32
#define WS      7
#define LW      49
#define NWIN    2048

// Scratch (device globals)
__device__ float g_qkv[(size_t)M_TOK * N_QKV];                 // 441 MB
__device__ float g_attn[(size_t)M_TOK * C_DIM];                // 147 MB
__device__ __nv_bfloat16 g_hi[(size_t)M_TOK * C_DIM];          // 77 MB (x, then attn)
__device__ __nv_bfloat16 g_lo[(size_t)M_TOK * C_DIM];
__device__ __nv_bfloat16 g_wh[(size_t)N_QKV * C_DIM];          // weights hi
__device__ __nv_bfloat16 g_wl[(size_t)N_QKV * C_DIM];          // weights lo

// ---------------------------------------------------------------------------
__device__ __forceinline__ uint32_t smem_u32(const void* p) {
    uint32_t a;
    asm("{ .reg .u64 t; cvta.to.shared.u64 t, %1; cvt.u32.u64 %0, t; }"
        : "=r"(a) : "l"(p));
    return a;
}
__device__ __forceinline__ void cp16(uint32_t dst, const void* src) {
    asm volatile("cp.async.cg.shared.global [%0], [%1], 16;" :: "r"(dst), "l"(src));
}
#define CP_COMMIT() asm volatile("cp.async.commit_group;" ::: "memory")
#define CP_WAIT(n)  asm volatile("cp.async.wait_group %0;" :: "n"(n) : "memory")

#define LDSM4(r0, r1, r2, r3, addr) \
    asm volatile("ldmatrix.sync.aligned.m8n8.x4.shared.b16 {%0,%1,%2,%3}, [%4];" \
                 : "=r"(r0), "=r"(r1), "=r"(r2), "=r"(r3) : "r"(addr))

#define MMA_BF16(acc, a, bb0, bb1) \
    asm volatile("mma.sync.aligned.m16n8k16.row.col.f32.bf16.bf16.f32 " \
                 "{%0,%1,%2,%3},{%4,%5,%6,%7},{%8,%9},{%0,%1,%2,%3};" \
                 : "+f"((acc)[0]), "+f"((acc)[1]), "+f"((acc)[2]), "+f"((acc)[3]) \
                 : "r"((a)[0]), "r"((a)[1]), "r"((a)[2]), "r"((a)[3]), \
                   "r"(bb0), "r"(bb1))

// ---------------------------------------------------------------------------
// Split fp32 -> bf16 hi + bf16 lo (residual)
// ---------------------------------------------------------------------------
__global__ __launch_bounds__(256) void split_hilo(
    const float* __restrict__ s, __nv_bfloat16* __restrict__ hi,
    __nv_bfloat16* __restrict__ lo, int n4)
{
    int i = blockIdx.x * blockDim.x + threadIdx.x;
    if (i >= n4) return;
    float4 v = ((const float4*)s)[i];
    __nv_bfloat16 h0 = __float2bfloat16_rn(v.x);
    __nv_bfloat16 h1 = __float2bfloat16_rn(v.y);
    __nv_bfloat16 h2 = __float2bfloat16_rn(v.z);
    __nv_bfloat16 h3 = __float2bfloat16_rn(v.w);
    __nv_bfloat16 l0 = __float2bfloat16_rn(v.x - __bfloat162float(h0));
    __nv_bfloat16 l1 = __float2bfloat16_rn(v.y - __bfloat162float(h1));
    __nv_bfloat16 l2 = __float2bfloat16_rn(v.z - __bfloat162float(h2));
    __nv_bfloat16 l3 = __float2bfloat16_rn(v.w - __bfloat162float(h3));
    __nv_bfloat162 hp0(h0, h1), hp1(h2, h3), lp0(l0, l1), lp1(l2, l3);
    uint2 hv, lv;
    hv.x = *reinterpret_cast<uint32_t*>(&hp0); hv.y = *reinterpret_cast<uint32_t*>(&hp1);
    lv.x = *reinterpret_cast<uint32_t*>(&lp0); lv.y = *reinterpret_cast<uint32_t*>(&lp1);
    ((uint2*)hi)[i] = hv;
    ((uint2*)lo)[i] = lv;
}

// ---------------------------------------------------------------------------
// bf16 hi/lo GEMM via mma.sync (tensor pipe): C[M,N] = A[M,384]*W[N,384]^T + b
// CTA 128x128, BK=32, 256 threads (8 warps as 2M x 4N, warp tile 64x32),
// cp.async double buffer. Smem rows padded to 80 B (conflict-free ldmatrix).
// ---------------------------------------------------------------------------
#define ROWB    80                     // bytes per 32-bf16 row (padded)
#define TILE_B  (128 * ROWB)           // 10240 B per tile
#define STAGE_B (4 * TILE_B)           // Ah, Al, Bh, Bl
#define SMEM_GEMM (2 * STAGE_B)        // 81920 B

__global__ __launch_bounds__(256, 1) void gemm_mma(
    const __nv_bfloat16* __restrict__ Ah, const __nv_bfloat16* __restrict__ Al,
    const __nv_bfloat16* __restrict__ Wh, const __nv_bfloat16* __restrict__ Wl,
    const float* __restrict__ bias, float* __restrict__ C, int N)
{
    extern __shared__ char smem[];
    const uint32_t sbase = smem_u32(smem);
    const int tid  = threadIdx.x;
    const int w    = tid >> 5;
    const int lane = tid & 31;
    const int bm = blockIdx.y, bn = blockIdx.x;

    const int wm = w >> 2;             // 0..1 -> M offset wm*64
    const int wn = w & 3;              // 0..3 -> N offset wn*32

    // gmem tile bases (bf16 elements)
    const __nv_bfloat16* tg[4];
    tg[0] = Ah + (size_t)bm * 128 * C_DIM;
    tg[1] = Al + (size_t)bm * 128 * C_DIM;
    tg[2] = Wh + (size_t)bn * 128 * C_DIM;
    tg[3] = Wl + (size_t)bn * 128 * C_DIM;

    // per-thread load slots: 512 16B-chunks per tile, 2 per thread
    const int r0 = (tid * 2) >> 2, c0 = (tid * 2) & 3;
    const int r1 = (tid * 2 + 1) >> 2, c1 = (tid * 2 + 1) & 3;

    float acc[4][4][4];
    #pragma unroll
    for (int i = 0; i < 4; i++)
        #pragma unroll
        for (int j = 0; j < 4; j++)
            #pragma unroll
            for (int q = 0; q < 4; q++) acc[i][j][q] = 0.0f;

    // ldmatrix per-lane address components
    const int aRow = (lane & 7) + ((lane >> 3) & 1) * 8;   // A/W m-row within 16
    const int aCk  = (lane >> 4) * 16;                     // A k-chunk byte off
    const int bRow = (lane & 7) + (lane >> 4) * 8;         // B n-row within 16
    const int bCk  = ((lane >> 3) & 1) * 16;               // B k-chunk byte off

    auto load_stage = [&](int it) {
        const int st = it & 1;
        const uint32_t sb = sbase + st * STAGE_B;
        const int k0 = it * 32;
        #pragma unroll
        for (int t = 0; t < 4; t++) {
            const __nv_bfloat16* g = tg[t] + k0;
            const uint32_t sm = sb + t * TILE_B;
            cp16(sm + r0 * ROWB + c0 * 16, g + (size_t)r0 * C_DIM + c0 * 8);
            cp16(sm + r1 * ROWB + c1 * 16, g + (size_t)r1 * C_DIM + c1 * 8);
        }
        CP_COMMIT();
    };

    load_stage(0);

    for (int it = 0; it < 12; it++) {
        if (it + 1 < 12) load_stage(it + 1);
        if (it + 1 < 12) { CP_WAIT(1); } else { CP_WAIT(0); }
        __syncthreads();

        const uint32_t sb = sbase + (it & 1) * STAGE_B;
        const uint32_t sAh = sb;
        const uint32_t sAl = sb + TILE_B;
        const uint32_t sBh = sb + 2 * TILE_B;
        const uint32_t sBl = sb + 3 * TILE_B;

        #pragma unroll
        for (int ks = 0; ks < 2; ks++) {
            const int kb = ks * 32;    // byte offset of k16 step (16 bf16)
            uint32_t ah[4][4], al[4][4], bh[2][4], bl[2][4];
            #pragma unroll
            for (int mt = 0; mt < 4; mt++) {
                const uint32_t ro = (uint32_t)(wm * 64 + mt * 16 + aRow) * ROWB + kb + aCk;
                LDSM4(ah[mt][0], ah[mt][1], ah[mt][2], ah[mt][3], sAh + ro);
                LDSM4(al[mt][0], al[mt][1], al[mt][2], al[mt][3], sAl + ro);
            }
            #pragma unroll
            for (int p = 0; p < 2; p++) {
                const uint32_t ro = (uint32_t)(wn * 32 + p * 16 + bRow) * ROWB + kb + bCk;
                LDSM4(bh[p][0], bh[p][1], bh[p][2], bh[p][3], sBh + ro);
                LDSM4(bl[p][0], bl[p][1], bl[p][2], bl[p][3], sBl + ro);
            }
            #pragma unroll
            for (int mt = 0; mt < 4; mt++)
                #pragma unroll
                for (int nt = 0; nt < 4; nt++) {
                    const int p = nt >> 1, f = (nt & 1) * 2;
                    MMA_BF16(acc[mt][nt], ah[mt], bh[p][f], bh[p][f + 1]);
                    MMA_BF16(acc[mt][nt], ah[mt], bl[p][f], bl[p][f + 1]);
                    MMA_BF16(acc[mt][nt], al[mt], bh[p][f], bh[p][f + 1]);
                }
        }
        __syncthreads();
    }

    // Epilogue: frag (c0,c1)->row lane/4, cols 2(lane%4); (c2,c3)->row+8
    const int er = lane >> 2, ec = (lane & 3) * 2;
    #pragma unroll
    for (int mt = 0; mt < 4; mt++) {
        #pragma unroll
        for (int nt = 0; nt < 4; nt++) {
            const size_t row = (size_t)bm * 128 + wm * 64 + mt * 16 + er;
            const int col = bn * 128 + wn * 32 + nt * 8 + ec;
            const float b0 = __ldg(bias + col), b1 = __ldg(bias + col + 1);
            float2 v0 = make_float2(acc[mt][nt][0] + b0, acc[mt][nt][1] + b1);
            float2 v1 = make_float2(acc[mt][nt][2] + b0, acc[mt][nt][3] + b1);
            *(float2*)(C + row * N + col) = v0;
            *(float2*)(C + (row + 8) * N + col) = v1;
        }
    }
}

// ---------------------------------------------------------------------------
// Window attention (unchanged; fp32 on g_qkv)
// ---------------------------------------------------------------------------
__global__ __launch_bounds__(64) void win_attn(void)
{
    const int head = blockIdx.x;
    const int win = blockIdx.y;
    const int b = win >> 6;
    const int wi = win & 63;
    const int wh = wi >> 3;
    const int ww = wi & 7;

    __shared__ float4 Qs[LW * 8];
    __shared__ float4 Ks[LW * 8];
    __shared__ float4 Vs[LW * 8];

    const int tid = threadIdx.x;
    const int head_off = head * HD;

    for (int idx = tid; idx < LW * 8; idx += 64) {
        const int j = idx >> 3;
        const int dd = idx & 7;
        const int r = j / WS, c = j % WS;
        const int l = (wh * WS + r) * HW + (ww * WS + c);
        const size_t base = ((size_t)b * L_TOK + l) * N_QKV + head_off + dd * 4;
        Qs[idx] = *(const float4*)(g_qkv + base);
        Ks[idx] = *(const float4*)(g_qkv + base + C_DIM);
        Vs[idx] = *(const float4*)(g_qkv + base + 2 * C_DIM);
    }
    __syncthreads();

    if (tid >= LW) return;
    const int i = tid;
    const float scale = 0.17677669529663687f;

    float4 q4[8];
    #pragma unroll
    for (int dd = 0; dd < 8; dd++) {
        float4 q = Qs[i * 8 + dd];
        q.x *= scale; q.y *= scale; q.z *= scale; q.w *= scale;
        q4[dd] = q;
    }

    float s[LW];
    float mx = -1e30f;
    #pragma unroll 7
    for (int j = 0; j < LW; j++) {
        float a = 0.0f;
        #pragma unroll
        for (int dd = 0; dd < 8; dd++) {
            const float4 k4 = Ks[j * 8 + dd];
            a = fmaf(q4[dd].x, k4.x, a);
            a = fmaf(q4[dd].y, k4.y, a);
            a = fmaf(q4[dd].z, k4.z, a);
            a = fmaf(q4[dd].w, k4.w, a);
        }
        s[j] = a;
        mx = fmaxf(mx, a);
    }

    float sum = 0.0f;
    #pragma unroll 7
    for (int j = 0; j < LW; j++) {
        const float e = __expf(s[j] - mx);
        s[j] = e;
        sum += e;
    }
    const float inv = 1.0f / sum;

    float4 o4[8];
    #pragma unroll
    for (int dd = 0; dd < 8; dd++) o4[dd] = make_float4(0.f, 0.f, 0.f, 0.f);

    #pragma unroll 7
    for (int j = 0; j < LW; j++) {
        const float p = s[j];
        #pragma unroll
        for (int dd = 0; dd < 8; dd++) {
            const float4 v4 = Vs[j * 8 + dd];
            o4[dd].x = fmaf(p, v4.x, o4[dd].x);
            o4[dd].y = fmaf(p, v4.y, o4[dd].y);
            o4[dd].z = fmaf(p, v4.z, o4[dd].z);
            o4[dd].w = fmaf(p, v4.w, o4[dd].w);
        }
    }

    const int r = i / WS, c = i % WS;
    const int l = (wh * WS + r) * HW + (ww * WS + c);
    float* dst = g_attn + ((size_t)b * L_TOK + l) * C_DIM + head_off;
    #pragma unroll
    for (int dd = 0; dd < 8; dd++) {
        float4 o = o4[dd];
        o.x *= inv; o.y *= inv; o.z *= inv; o.w *= inv;
        ((float4*)dst)[dd] = o;
    }
}

// ---------------------------------------------------------------------------
extern "C" void kernel_launch(void* const* d_in, const int* in_sizes, int n_in,
                              void* d_out, int out_size)
{
    const float* x      = (const float*)d_in[0];
    const float* qkv_w  = (const float*)d_in[1];
    const float* qkv_b  = (const float*)d_in[2];
    const float* proj_w = (const float*)d_in[3];
    const float* proj_b = (const float*)d_in[4];
    float* out = (float*)d_out;

    float* qkv_buf = nullptr; float* attn_buf = nullptr;
    __nv_bfloat16 *hi, *lo, *wh, *wl;
    cudaGetSymbolAddress((void**)&qkv_buf, g_qkv);
    cudaGetSymbolAddress((void**)&attn_buf, g_attn);
    cudaGetSymbolAddress((void**)&hi, g_hi);
    cudaGetSymbolAddress((void**)&lo, g_lo);
    cudaGetSymbolAddress((void**)&wh, g_wh);
    cudaGetSymbolAddress((void**)&wl, g_wl);

    cudaFuncSetAttribute(gemm_mma, cudaFuncAttributeMaxDynamicSharedMemorySize, SMEM_GEMM);

    const int nx4 = M_TOK * C_DIM / 4;
    const int nwq4 = N_QKV * C_DIM / 4;
    const int nwp4 = C_DIM * C_DIM / 4;

    // 1) Split x and qkv_w into bf16 hi/lo
    split_hilo<<<(nx4 + 255) / 256, 256>>>(x, hi, lo, nx4);
    split_hilo<<<(nwq4 + 255) / 256, 256>>>(qkv_w, wh, wl, nwq4);

    // 2) QKV GEMM (tensor pipe): [100352,384] x [1152,384]^T
    {
        dim3 grid(N_QKV / 128, M_TOK / 128);   // (9, 784)
        gemm_mma<<<grid, 256, SMEM_GEMM>>>(hi, lo, wh, wl, qkv_b, qkv_buf, N_QKV);
    }
    // 3) Windowed attention
    {
        dim3 grid(HEADS, NWIN);
        win_attn<<<grid, 64>>>();
    }
    // 4) Split attention output and proj_w
    split_hilo<<<(nx4 + 255) / 256, 256>>>(attn_buf, hi, lo, nx4);
    split_hilo<<<(nwp4 + 255) / 256, 256>>>(proj_w, wh, wl, nwp4);

    // 5) Proj GEMM: [100352,384] x [384,384]^T
    {
        dim3 grid(C_DIM / 128, M_TOK / 128);   // (3, 784)
        gemm_mma<<<grid, 256, SMEM_GEMM>>>(hi, lo, wh, wl, proj_b, out, C_DIM);
    }
}

// round 7
// speedup vs baseline: 1.8299x; 1.3703x over previous
#include <cuda_runtime.h>
#include <cuda_bf16.h>
#include <cstdint>

// Problem constants (B=32, H=W=56, C=384, heads=12, ws=7)
#define HW      56
#define L_TOK   3136
#define M_TOK   100352
#define C_DIM   384
#define N_QKV   1152
#define HEADS   12
#define HD      32
#define WS      7
#define LW      49
#define NWIN    2048

// Scratch (device globals)
__device__ float g_qkv[(size_t)M_TOK * N_QKV];                 // 441 MB
__device__ __nv_bfloat16 g_hi[(size_t)M_TOK * C_DIM];          // 77 MB (x, then attn out)
__device__ __nv_bfloat16 g_lo[(size_t)M_TOK * C_DIM];
__device__ __nv_bfloat16 g_wh[(size_t)N_QKV * C_DIM];          // weights hi
__device__ __nv_bfloat16 g_wl[(size_t)N_QKV * C_DIM];          // weights lo

// ---------------------------------------------------------------------------
__device__ __forceinline__ uint32_t smem_u32(const void* p) {
    uint32_t a;
    asm("{ .reg .u64 t; cvta.to.shared.u64 t, %1; cvt.u32.u64 %0, t; }"
        : "=r"(a) : "l"(p));
    return a;
}
__device__ __forceinline__ void cp16(uint32_t dst, const void* src) {
    asm volatile("cp.async.cg.shared.global [%0], [%1], 16;" :: "r"(dst), "l"(src));
}
#define CP_COMMIT() asm volatile("cp.async.commit_group;" ::: "memory")
#define CP_WAIT(n)  asm volatile("cp.async.wait_group %0;" :: "n"(n) : "memory")

#define LDSM4(r0, r1, r2, r3, addr) \
    asm volatile("ldmatrix.sync.aligned.m8n8.x4.shared.b16 {%0,%1,%2,%3}, [%4];" \
                 : "=r"(r0), "=r"(r1), "=r"(r2), "=r"(r3) : "r"(addr))

#define MMA_BF16(acc, a, bb0, bb1) \
    asm volatile("mma.sync.aligned.m16n8k16.row.col.f32.bf16.bf16.f32 " \
                 "{%0,%1,%2,%3},{%4,%5,%6,%7},{%8,%9},{%0,%1,%2,%3};" \
                 : "+f"((acc)[0]), "+f"((acc)[1]), "+f"((acc)[2]), "+f"((acc)[3]) \
                 : "r"((a)[0]), "r"((a)[1]), "r"((a)[2]), "r"((a)[3]), \
                   "r"(bb0), "r"(bb1))

// ---------------------------------------------------------------------------
// Split fp32 -> bf16 hi + bf16 lo (residual)
// ---------------------------------------------------------------------------
__global__ __launch_bounds__(256) void split_hilo(
    const float* __restrict__ s, __nv_bfloat16* __restrict__ hi,
    __nv_bfloat16* __restrict__ lo, int n4)
{
    int i = blockIdx.x * blockDim.x + threadIdx.x;
    if (i >= n4) return;
    float4 v = ((const float4*)s)[i];
    __nv_bfloat16 h0 = __float2bfloat16_rn(v.x);
    __nv_bfloat16 h1 = __float2bfloat16_rn(v.y);
    __nv_bfloat16 h2 = __float2bfloat16_rn(v.z);
    __nv_bfloat16 h3 = __float2bfloat16_rn(v.w);
    __nv_bfloat16 l0 = __float2bfloat16_rn(v.x - __bfloat162float(h0));
    __nv_bfloat16 l1 = __float2bfloat16_rn(v.y - __bfloat162float(h1));
    __nv_bfloat16 l2 = __float2bfloat16_rn(v.z - __bfloat162float(h2));
    __nv_bfloat16 l3 = __float2bfloat16_rn(v.w - __bfloat162float(h3));
    __nv_bfloat162 hp0(h0, h1), hp1(h2, h3), lp0(l0, l1), lp1(l2, l3);
    uint2 hv, lv;
    hv.x = *reinterpret_cast<uint32_t*>(&hp0); hv.y = *reinterpret_cast<uint32_t*>(&hp1);
    lv.x = *reinterpret_cast<uint32_t*>(&lp0); lv.y = *reinterpret_cast<uint32_t*>(&lp1);
    ((uint2*)hi)[i] = hv;
    ((uint2*)lo)[i] = lv;
}

// ---------------------------------------------------------------------------
// bf16 hi/lo GEMM via mma.sync: C[M,N] = A[M,384]*W[N,384]^T + bias
// CTA 128x128, BK=32, 256 threads (8 warps as 2M x 4N, warp tile 64x32),
// cp.async TRIPLE buffer. Smem rows padded to 80 B (conflict-free ldmatrix).
// ---------------------------------------------------------------------------
#define ROWB    80                     // bytes per 32-bf16 row (padded)
#define TILE_B  (128 * ROWB)           // 10240 B per tile
#define STAGE_B (4 * TILE_B)           // Ah, Al, Bh, Bl
#define NSTAGE  3
#define SMEM_GEMM (NSTAGE * STAGE_B)   // 122880 B

__global__ __launch_bounds__(256, 1) void gemm_mma(
    const __nv_bfloat16* __restrict__ Ah, const __nv_bfloat16* __restrict__ Al,
    const __nv_bfloat16* __restrict__ Wh, const __nv_bfloat16* __restrict__ Wl,
    const float* __restrict__ bias, float* __restrict__ C, int N)
{
    extern __shared__ char smem[];
    const uint32_t sbase = smem_u32(smem);
    const int tid  = threadIdx.x;
    const int w    = tid >> 5;
    const int lane = tid & 31;
    const int bm = blockIdx.y, bn = blockIdx.x;

    const int wm = w >> 2;             // 0..1 -> M offset wm*64
    const int wn = w & 3;              // 0..3 -> N offset wn*32

    const __nv_bfloat16* tg[4];
    tg[0] = Ah + (size_t)bm * 128 * C_DIM;
    tg[1] = Al + (size_t)bm * 128 * C_DIM;
    tg[2] = Wh + (size_t)bn * 128 * C_DIM;
    tg[3] = Wl + (size_t)bn * 128 * C_DIM;

    // per-thread load slots: 512 16B-chunks per tile, 2 per thread
    const int r0 = (tid * 2) >> 2, c0 = (tid * 2) & 3;
    const int r1 = (tid * 2 + 1) >> 2, c1 = (tid * 2 + 1) & 3;

    float acc[4][4][4];
    #pragma unroll
    for (int i = 0; i < 4; i++)
        #pragma unroll
        for (int j = 0; j < 4; j++)
            #pragma unroll
            for (int q = 0; q < 4; q++) acc[i][j][q] = 0.0f;

    const int aRow = (lane & 7) + ((lane >> 3) & 1) * 8;
    const int aCk  = (lane >> 4) * 16;
    const int bRow = (lane & 7) + (lane >> 4) * 8;
    const int bCk  = ((lane >> 3) & 1) * 16;

    auto load_stage = [&](int it) {
        const int st = it % NSTAGE;
        const uint32_t sb = sbase + st * STAGE_B;
        const int k0 = it * 32;
        #pragma unroll
        for (int t = 0; t < 4; t++) {
            const __nv_bfloat16* g = tg[t] + k0;
            const uint32_t sm = sb + t * TILE_B;
            cp16(sm + r0 * ROWB + c0 * 16, g + (size_t)r0 * C_DIM + c0 * 8);
            cp16(sm + r1 * ROWB + c1 * 16, g + (size_t)r1 * C_DIM + c1 * 8);
        }
        CP_COMMIT();
    };

    load_stage(0);
    load_stage(1);

    for (int it = 0; it < 12; it++) {
        if (it + 2 < 12) { load_stage(it + 2); CP_WAIT(2); }
        else if (it + 1 < 12) { CP_WAIT(1); }
        else { CP_WAIT(0); }
        __syncthreads();

        const uint32_t sb = sbase + (it % NSTAGE) * STAGE_B;
        const uint32_t sAh = sb;
        const uint32_t sAl = sb + TILE_B;
        const uint32_t sBh = sb + 2 * TILE_B;
        const uint32_t sBl = sb + 3 * TILE_B;

        #pragma unroll
        for (int ks = 0; ks < 2; ks++) {
            const int kb = ks * 32;
            uint32_t ah[4][4], al[4][4], bh[2][4], bl[2][4];
            #pragma unroll
            for (int mt = 0; mt < 4; mt++) {
                const uint32_t ro = (uint32_t)(wm * 64 + mt * 16 + aRow) * ROWB + kb + aCk;
                LDSM4(ah[mt][0], ah[mt][1], ah[mt][2], ah[mt][3], sAh + ro);
                LDSM4(al[mt][0], al[mt][1], al[mt][2], al[mt][3], sAl + ro);
            }
            #pragma unroll
            for (int p = 0; p < 2; p++) {
                const uint32_t ro = (uint32_t)(wn * 32 + p * 16 + bRow) * ROWB + kb + bCk;
                LDSM4(bh[p][0], bh[p][1], bh[p][2], bh[p][3], sBh + ro);
                LDSM4(bl[p][0], bl[p][1], bl[p][2], bl[p][3], sBl + ro);
            }
            #pragma unroll
            for (int mt = 0; mt < 4; mt++)
                #pragma unroll
                for (int nt = 0; nt < 4; nt++) {
                    const int p = nt >> 1, f = (nt & 1) * 2;
                    MMA_BF16(acc[mt][nt], ah[mt], bh[p][f], bh[p][f + 1]);
                    MMA_BF16(acc[mt][nt], ah[mt], bl[p][f], bl[p][f + 1]);
                    MMA_BF16(acc[mt][nt], al[mt], bh[p][f], bh[p][f + 1]);
                }
        }
        __syncthreads();
    }

    const int er = lane >> 2, ec = (lane & 3) * 2;
    #pragma unroll
    for (int mt = 0; mt < 4; mt++) {
        #pragma unroll
        for (int nt = 0; nt < 4; nt++) {
            const size_t row = (size_t)bm * 128 + wm * 64 + mt * 16 + er;
            const int col = bn * 128 + wn * 32 + nt * 8 + ec;
            const float b0 = __ldg(bias + col), b1 = __ldg(bias + col + 1);
            float2 v0 = make_float2(acc[mt][nt][0] + b0, acc[mt][nt][1] + b1);
            float2 v1 = make_float2(acc[mt][nt][2] + b0, acc[mt][nt][3] + b1);
            *(float2*)(C + row * N + col) = v0;
            *(float2*)(C + (row + 8) * N + col) = v1;
        }
    }
}

// ---------------------------------------------------------------------------
// Window attention v2: no Q staging (regs), K/V in smem (12.5 KB/block).
// Epilogue writes bf16 hi/lo directly (fused split for proj GEMM input).
// ---------------------------------------------------------------------------
__global__ __launch_bounds__(64) void win_attn(void)
{
    const int head = blockIdx.x;
    const int win = blockIdx.y;
    const int b = win >> 6;
    const int wi = win & 63;
    const int wh = wi >> 3;
    const int ww = wi & 7;

    __shared__ float4 Ks[LW * 8];
    __shared__ float4 Vs[LW * 8];

    const int tid = threadIdx.x;
    const int head_off = head * HD;

    // Stage K and V for this window/head
    for (int idx = tid; idx < LW * 8; idx += 64) {
        const int j = idx >> 3;
        const int dd = idx & 7;
        const int r = j / WS, c = j % WS;
        const int l = (wh * WS + r) * HW + (ww * WS + c);
        const size_t base = ((size_t)b * L_TOK + l) * N_QKV + head_off + dd * 4;
        Ks[idx] = *(const float4*)(g_qkv + base + C_DIM);
        Vs[idx] = *(const float4*)(g_qkv + base + 2 * C_DIM);
    }
    __syncthreads();

    if (tid >= LW) return;
    const int i = tid;
    const float scale = 0.17677669529663687f;

    // Read own Q row straight to registers
    const int r = i / WS, c = i % WS;
    const int l = (wh * WS + r) * HW + (ww * WS + c);
    const float* qptr = g_qkv + ((size_t)b * L_TOK + l) * N_QKV + head_off;

    float4 q4[8];
    #pragma unroll
    for (int dd = 0; dd < 8; dd++) {
        float4 q = ((const float4*)qptr)[dd];
        q.x *= scale; q.y *= scale; q.z *= scale; q.w *= scale;
        q4[dd] = q;
    }

    float s[LW];
    float mx = -1e30f;
    #pragma unroll 7
    for (int j = 0; j < LW; j++) {
        float a = 0.0f;
        #pragma unroll
        for (int dd = 0; dd < 8; dd++) {
            const float4 k4 = Ks[j * 8 + dd];
            a = fmaf(q4[dd].x, k4.x, a);
            a = fmaf(q4[dd].y, k4.y, a);
            a = fmaf(q4[dd].z, k4.z, a);
            a = fmaf(q4[dd].w, k4.w, a);
        }
        s[j] = a;
        mx = fmaxf(mx, a);
    }

    float sum = 0.0f;
    #pragma unroll 7
    for (int j = 0; j < LW; j++) {
        const float e = __expf(s[j] - mx);
        s[j] = e;
        sum += e;
    }
    const float inv = 1.0f / sum;

    float4 o4[8];
    #pragma unroll
    for (int dd = 0; dd < 8; dd++) o4[dd] = make_float4(0.f, 0.f, 0.f, 0.f);

    #pragma unroll 7
    for (int j = 0; j < LW; j++) {
        const float p = s[j];
        #pragma unroll
        for (int dd = 0; dd < 8; dd++) {
            const float4 v4 = Vs[j * 8 + dd];
            o4[dd].x = fmaf(p, v4.x, o4[dd].x);
            o4[dd].y = fmaf(p, v4.y, o4[dd].y);
            o4[dd].z = fmaf(p, v4.z, o4[dd].z);
            o4[dd].w = fmaf(p, v4.w, o4[dd].w);
        }
    }

    // Fused hi/lo epilogue: write bf16 hi + lo (proj GEMM inputs)
    const size_t obase = ((size_t)b * L_TOK + l) * C_DIM + head_off;
    __nv_bfloat16* dh = g_hi + obase;
    __nv_bfloat16* dl = g_lo + obase;
    #pragma unroll
    for (int dd = 0; dd < 8; dd++) {
        float4 o = o4[dd];
        o.x *= inv; o.y *= inv; o.z *= inv; o.w *= inv;
        __nv_bfloat16 h0 = __float2bfloat16_rn(o.x);
        __nv_bfloat16 h1 = __float2bfloat16_rn(o.y);
        __nv_bfloat16 h2 = __float2bfloat16_rn(o.z);
        __nv_bfloat16 h3 = __float2bfloat16_rn(o.w);
        __nv_bfloat16 l0 = __float2bfloat16_rn(o.x - __bfloat162float(h0));
        __nv_bfloat16 l1 = __float2bfloat16_rn(o.y - __bfloat162float(h1));
        __nv_bfloat16 l2 = __float2bfloat16_rn(o.z - __bfloat162float(h2));
        __nv_bfloat16 l3 = __float2bfloat16_rn(o.w - __bfloat162float(h3));
        __nv_bfloat162 hp0(h0, h1), hp1(h2, h3), lp0(l0, l1), lp1(l2, l3);
        uint2 hv, lv;
        hv.x = *reinterpret_cast<uint32_t*>(&hp0);
        hv.y = *reinterpret_cast<uint32_t*>(&hp1);
        lv.x = *reinterpret_cast<uint32_t*>(&lp0);
        lv.y = *reinterpret_cast<uint32_t*>(&lp1);
        ((uint2*)dh)[dd] = hv;
        ((uint2*)dl)[dd] = lv;
    }
}

// ---------------------------------------------------------------------------
extern "C" void kernel_launch(void* const* d_in, const int* in_sizes, int n_in,
                              void* d_out, int out_size)
{
    const float* x      = (const float*)d_in[0];
    const float* qkv_w  = (const float*)d_in[1];
    const float* qkv_b  = (const float*)d_in[2];
    const float* proj_w = (const float*)d_in[3];
    const float* proj_b = (const float*)d_in[4];
    float* out = (float*)d_out;

    float* qkv_buf = nullptr;
    __nv_bfloat16 *hi, *lo, *wh, *wl;
    cudaGetSymbolAddress((void**)&qkv_buf, g_qkv);
    cudaGetSymbolAddress((void**)&hi, g_hi);
    cudaGetSymbolAddress((void**)&lo, g_lo);
    cudaGetSymbolAddress((void**)&wh, g_wh);
    cudaGetSymbolAddress((void**)&wl, g_wl);

    cudaFuncSetAttribute(gemm_mma, cudaFuncAttributeMaxDynamicSharedMemorySize, SMEM_GEMM);

    const int nx4 = M_TOK * C_DIM / 4;
    const int nwq4 = N_QKV * C_DIM / 4;
    const int nwp4 = C_DIM * C_DIM / 4;

    // 1) Split x and qkv_w into bf16 hi/lo
    split_hilo<<<(nx4 + 255) / 256, 256>>>(x, hi, lo, nx4);
    split_hilo<<<(nwq4 + 255) / 256, 256>>>(qkv_w, wh, wl, nwq4);

    // 2) QKV GEMM (tensor pipe): [100352,384] x [1152,384]^T
    {
        dim3 grid(N_QKV / 128, M_TOK / 128);   // (9, 784)
        gemm_mma<<<grid, 256, SMEM_GEMM>>>(hi, lo, wh, wl, qkv_b, qkv_buf, N_QKV);
    }
    // 3) Windowed attention (writes hi/lo directly)
    {
        dim3 grid(HEADS, NWIN);
        win_attn<<<grid, 64>>>();
    }
    // 4) Split proj_w only (attn hi/lo already written by win_attn)
    split_hilo<<<(nwp4 + 255) / 256, 256>>>(proj_w, wh, wl, nwp4);

    // 5) Proj GEMM: [100352,384] x [384,384]^T
    {
        dim3 grid(C_DIM / 128, M_TOK / 128);   // (3, 784)
        gemm_mma<<<grid, 256, SMEM_GEMM>>>(hi, lo, wh, wl, proj_b, out, C_DIM);
    }
}